// round 14
// baseline (speedup 1.0000x reference)
#include <cuda_runtime.h>
#include <cuda_bf16.h>
#include <cstdint>
#include <cstddef>

#define TT 512
#define NBATCH 256
#define EE 256
#define HH 256
#define GG 1024
#define NBLK 128
#define GSIZE 8          // CTAs per row-group (bj = 0..7)
#define NGROUPS 16       // row groups (bn = 0..15)

typedef unsigned long long ull;
union F2U { ull u; float2 f; };

// ---- packed f32x2 helpers (Blackwell FFMA2 — PTX-only) ----
__device__ __forceinline__ ull bcast2(float x) {
    ull r; asm("mov.b64 %0, {%1, %1};" : "=l"(r) : "f"(x)); return r;
}
__device__ __forceinline__ ull pack2(float lo, float hi) {
    ull r; asm("mov.b64 %0, {%1, %2};" : "=l"(r) : "f"(lo), "f"(hi)); return r;
}
__device__ __forceinline__ void ffma2(ull& d, ull a, ull b) {
    asm("fma.rn.f32x2 %0, %1, %2, %0;" : "+l"(d) : "l"(a), "l"(b));
}

// ---- warp-MMA helpers (baseline sm_100: ldmatrix + mma.sync, NO tcgen05) ----
__device__ __forceinline__ uint32_t smem_u32(const void* p) {
    uint32_t a;
    asm("{ .reg .u64 t; cvta.to.shared.u64 t, %1; cvt.u32.u64 %0, t; }" : "=r"(a) : "l"(p));
    return a;
}
__device__ __forceinline__ void ldsm_x4(uint32_t* r, uint32_t addr) {
    asm volatile("ldmatrix.sync.aligned.m8n8.x4.shared.b16 {%0,%1,%2,%3}, [%4];"
                 : "=r"(r[0]), "=r"(r[1]), "=r"(r[2]), "=r"(r[3]) : "r"(addr));
}
// B tiles are [n][k] row-major (k contiguous) == col-major k x n => NON-trans ldmatrix.
__device__ __forceinline__ void ldsm_x2(uint32_t* r, uint32_t addr) {
    asm volatile("ldmatrix.sync.aligned.m8n8.x2.shared.b16 {%0,%1}, [%2];"
                 : "=r"(r[0]), "=r"(r[1]) : "r"(addr));
}
__device__ __forceinline__ void mma16816(float* d, const uint32_t* a, const uint32_t* b) {
    asm volatile(
        "mma.sync.aligned.m16n8k16.row.col.f32.bf16.bf16.f32 "
        "{%0,%1,%2,%3}, {%4,%5,%6,%7}, {%8,%9}, {%0,%1,%2,%3};"
        : "+f"(d[0]), "+f"(d[1]), "+f"(d[2]), "+f"(d[3])
        : "r"(a[0]), "r"(a[1]), "r"(a[2]), "r"(a[3]), "r"(b[0]), "r"(b[1]));
}
__device__ __forceinline__ uint32_t sw128(uint32_t bo) { return bo ^ ((bo >> 3) & 0x70); }

// ---------------- device scratch ----------------
__device__ __align__(16) float g_xg[(size_t)TT * NBATCH * GG];   // xg[t][n][g]
__device__ __align__(16) float g_hbuf[2][NBATCH * HH];           // double-buffered h
__device__ __align__(128) unsigned int g_gbar[NGROUPS * 32];     // per-group tickets

// split f32 -> (hi, lo) bf16 pairs, store 8B to each tile at swizzled offset
__device__ __forceinline__ void split_store(char* hi_p, char* lo_p, float4 v) {
    __nv_bfloat16 hx = __float2bfloat16(v.x), hy = __float2bfloat16(v.y),
                  hz = __float2bfloat16(v.z), hw = __float2bfloat16(v.w);
    __nv_bfloat16 lx = __float2bfloat16(v.x - __bfloat162float(hx));
    __nv_bfloat16 ly = __float2bfloat16(v.y - __bfloat162float(hy));
    __nv_bfloat16 lz = __float2bfloat16(v.z - __bfloat162float(hz));
    __nv_bfloat16 lw = __float2bfloat16(v.w - __bfloat162float(hw));
    union { __nv_bfloat162 b[2]; uint2 u; } H, L;
    H.b[0] = __halves2bfloat162(hx, hy); H.b[1] = __halves2bfloat162(hz, hw);
    L.b[0] = __halves2bfloat162(lx, ly); L.b[1] = __halves2bfloat162(lz, lw);
    *(uint2*)hi_p = H.u;
    *(uint2*)lo_p = L.u;
}

// ---------------- phase 1: xg = x @ Wih^T + biases via split-bf16 mma.sync ----------------
// 128(M) x 128(N) tile per CTA, K=256 in 4 chunks of 64. Per chunk: f32 -> hi/lo bf16
// SW128 smem tiles, then 3 product combos (hi.hi + hi.lo + lo.hi) of m16n8k16 bf16
// mma.sync, f32 register accumulators. 8 warps in 2(M) x 4(N), 64x32 warp tile.
// Fused graph-replay state reset retained.
__global__ void __launch_bounds__(256, 2) xg_gemm_kernel(
    const float* __restrict__ attn,   // (N, T, E)
    const float* __restrict__ Wih,    // (4H, E)
    const float* __restrict__ bih,
    const float* __restrict__ bhh) {
    extern __shared__ char dsm[];     // 4 tiles x 16KB: aHi aLo bHi bLo
    __shared__ float sbias[128];

    const int gt = blockIdx.x;                 // 0..7
    const int mt = blockIdx.y;                 // 0..1023
    const int t  = mt >> 1;
    const int n0 = (mt & 1) << 7;
    const int g0 = gt << 7;
    const int tid = threadIdx.x;
    const int wid = tid >> 5, lane = tid & 31;

    // fused graph-replay-safe reset
    if (gt == 0) {
        if (mt < 64) {
            int i = (mt << 8) + tid;
            *(float4*)&g_hbuf[0][i << 2] = make_float4(0.f, 0.f, 0.f, 0.f);
        } else if (mt == 64) {
            g_gbar[tid] = 0u;
            g_gbar[tid + 256] = 0u;
        }
    }

    char* aHi = dsm;
    char* aLo = dsm + 16384;
    char* bHi = dsm + 32768;
    char* bLo = dsm + 49152;
    const uint32_t uaHi = smem_u32(aHi), uaLo = uaHi + 16384;
    const uint32_t ubHi = uaHi + 32768, ubLo = uaHi + 49152;

    if (tid < 128) sbias[tid] = bih[g0 + tid] + bhh[g0 + tid];

    const int m_base = (wid & 1) << 6;         // 0 or 64
    const int nb     = (wid >> 1) << 5;        // 0,32,64,96

    float d[4][4][4];
#pragma unroll
    for (int mi = 0; mi < 4; mi++)
#pragma unroll
        for (int ni = 0; ni < 4; ni++)
#pragma unroll
            for (int q = 0; q < 4; q++) d[mi][ni][q] = 0.f;

    const int lrow = tid >> 1;                 // 0..127
    const int lhalf = (tid & 1) << 5;          // 0 or 32
    const float* aP = attn + ((size_t)(n0 + lrow) * TT + t) * EE + lhalf;
    const float* bP = Wih + (size_t)(g0 + lrow) * EE + lhalf;

    // per-lane ldmatrix offset components
    const int a_r = lane & 15;                 // A: row within m16
    const int a_c = (lane >> 4) << 3;          // A: k offset 0/8
    const int b_r = lane & 7;                  // B: row within n8 (lanes 0-15 used)
    const int b_c = ((lane >> 3) & 1) << 3;    // B: k offset 0 (matrix0) / 8 (matrix1)

#pragma unroll 1
    for (int ch = 0; ch < 4; ch++) {
        if (ch > 0) __syncthreads();           // prior chunk's mma reads done
        const int k0g = ch << 6;
#pragma unroll
        for (int j = 0; j < 8; j++) {
            float4 va = *(const float4*)(aP + k0g + (j << 2));
            float4 vb = *(const float4*)(bP + k0g + (j << 2));
            uint32_t so = sw128((lrow << 7) + ((lhalf + (j << 2)) << 1));
            split_store(aHi + so, aLo + so, va);
            split_store(bHi + so, bLo + so, vb);
        }
        __syncthreads();

#pragma unroll
        for (int combo = 0; combo < 3; combo++) {
            const uint32_t aBase = (combo == 2) ? uaLo : uaHi;
            const uint32_t bBase = (combo == 1) ? ubLo : ubHi;
#pragma unroll
            for (int k16 = 0; k16 < 4; k16++) {
                const int kc = k16 << 4;
                uint32_t afr[4][4];
#pragma unroll
                for (int mi = 0; mi < 4; mi++) {
                    uint32_t bo = ((m_base + (mi << 4) + a_r) << 7) + ((kc + a_c) << 1);
                    ldsm_x4(afr[mi], aBase + sw128(bo));
                }
                uint32_t bfr[4][2];
#pragma unroll
                for (int ni = 0; ni < 4; ni++) {
                    uint32_t bo = ((nb + (ni << 3) + b_r) << 7) + ((kc + b_c) << 1);
                    ldsm_x2(bfr[ni], bBase + sw128(bo));
                }
#pragma unroll
                for (int mi = 0; mi < 4; mi++)
#pragma unroll
                    for (int ni = 0; ni < 4; ni++)
                        mma16816(d[mi][ni], afr[mi], bfr[ni]);
            }
        }
    }

    // epilogue: accum regs -> bias -> g_xg
    const int gID = lane >> 2, t4 = lane & 3;
#pragma unroll
    for (int mi = 0; mi < 4; mi++) {
        const int row0 = m_base + (mi << 4) + gID;
#pragma unroll
        for (int ni = 0; ni < 4; ni++) {
            const int col = nb + (ni << 3) + (t4 << 1);
            const float bx = sbias[col], by = sbias[col + 1];
            size_t base0 = ((size_t)t * NBATCH + (n0 + row0)) * GG + g0 + col;
            size_t base1 = base0 + (size_t)8 * GG;      // row0 + 8
            *(float2*)&g_xg[base0] = make_float2(d[mi][ni][0] + bx, d[mi][ni][1] + by);
            *(float2*)&g_xg[base1] = make_float2(d[mi][ni][2] + bx, d[mi][ni][3] + by);
        }
    }
}

#define XG_SMEM_BYTES 65536

// ---------------- phase 2: persistent recurrent kernel (unchanged, validated) ----------------
__device__ __forceinline__ float sigf(float x) { return 1.0f / (1.0f + __expf(-x)); }
__device__ __forceinline__ float tanh_fast(float x) { return 1.0f - 2.0f / (__expf(2.0f * x) + 1.0f); }

__global__ void __launch_bounds__(256, 1) lstm_rec_kernel(
    const float* __restrict__ Whh,       // (4H, H)
    const int*   __restrict__ traj_len,  // (N,)
    float*       __restrict__ out) {     // (N, 1, H)
    extern __shared__ float red[];       // 64 KB dynamic
    __shared__ float hs[16 * 256];       // staged h tile (16 KB)
    __shared__ int slen[16];

    const int tid = threadIdx.x;
    const int bid = blockIdx.x;
    const int bn = bid & 15, bj = bid >> 4;
    const int r0 = bn << 4;
    const int c0 = bj << 5;
    const int ks = tid >> 5, gcg = tid & 31;

    ull pwA[32], pwB[32];
    {
        const float* wr[4];
#pragma unroll
        for (int q = 0; q < 4; q++) {
            int l = (gcg << 2) + q;
            int gr = ((l >> 5) << 8) + c0 + (l & 31);
            wr[q] = &Whh[(size_t)gr * HH + (ks << 5)];
        }
#pragma unroll
        for (int kc = 0; kc < 8; kc++) {
            float4 w0 = *(const float4*)(wr[0] + (kc << 2));
            float4 w1 = *(const float4*)(wr[1] + (kc << 2));
            float4 w2 = *(const float4*)(wr[2] + (kc << 2));
            float4 w3 = *(const float4*)(wr[3] + (kc << 2));
            pwA[(kc << 2) + 0] = pack2(w0.x, w1.x);
            pwA[(kc << 2) + 1] = pack2(w0.y, w1.y);
            pwA[(kc << 2) + 2] = pack2(w0.z, w1.z);
            pwA[(kc << 2) + 3] = pack2(w0.w, w1.w);
            pwB[(kc << 2) + 0] = pack2(w2.x, w3.x);
            pwB[(kc << 2) + 1] = pack2(w2.y, w3.y);
            pwB[(kc << 2) + 2] = pack2(w2.z, w3.z);
            pwB[(kc << 2) + 3] = pack2(w2.w, w3.w);
        }
    }

    if (tid < 16) slen[tid] = traj_len[r0 + tid];

    const int er = tid >> 4, ep = tid & 15;
    const int n_e = r0 + er;
    const int len_e = traj_len[n_e];
    const int col_e = c0 + (ep << 1);
    float cc0 = 0.f, cc1 = 0.f, hk0 = 0.f, hk1 = 0.f;

    unsigned int* barp = &g_gbar[bn << 5];
    __syncthreads();

    int gmax = 0;
#pragma unroll
    for (int r = 0; r < 16; r++) gmax = max(gmax, slen[r]);

    for (int t = 0; t < gmax; t++) {
        const bool valid = (t < len_e);

        float2 xi, xf, xg2, xo;
        if (valid) {
            const float* xgp = &g_xg[((size_t)t * NBATCH + n_e) * GG + col_e];
            xi  = __ldcs((const float2*)&xgp[0]);
            xf  = __ldcs((const float2*)&xgp[256]);
            xg2 = __ldcs((const float2*)&xgp[512]);
            xo  = __ldcs((const float2*)&xgp[768]);
        }

        if (t > 0) {
            if (tid == 0) {
                const unsigned target = (unsigned)t * GSIZE;
                unsigned v;
                do {
                    asm volatile("ld.acquire.gpu.global.u32 %0, [%1];"
                                 : "=r"(v) : "l"(barp) : "memory");
                } while (v < target);
            }
            __syncthreads();
        }

        {
            const float4* src = (const float4*)&g_hbuf[t & 1][r0 << 8];
#pragma unroll
            for (int q = 0; q < 4; q++) {
                int i = (q << 8) + tid;
                float4 v = __ldcg(src + i);
                *(float4*)&hs[i << 2] = v;
            }
        }
        __syncthreads();

#pragma unroll 2
        for (int r = 0; r < 16; r++) {
            if (t < slen[r]) {
                const float4* hp = (const float4*)&hs[(r << 8) + (ks << 5)];
                ull accA = 0ull, accB = 0ull;
#pragma unroll
                for (int kc = 0; kc < 8; kc++) {
                    float4 hv = hp[kc];
                    ull h0 = bcast2(hv.x), h1 = bcast2(hv.y), h2 = bcast2(hv.z), h3 = bcast2(hv.w);
                    ffma2(accA, h0, pwA[(kc << 2) + 0]); ffma2(accB, h0, pwB[(kc << 2) + 0]);
                    ffma2(accA, h1, pwA[(kc << 2) + 1]); ffma2(accB, h1, pwB[(kc << 2) + 1]);
                    ffma2(accA, h2, pwA[(kc << 2) + 2]); ffma2(accB, h2, pwB[(kc << 2) + 2]);
                    ffma2(accA, h3, pwA[(kc << 2) + 3]); ffma2(accB, h3, pwB[(kc << 2) + 3]);
                }
                ulonglong2 st; st.x = accA; st.y = accB;
                *(ulonglong2*)&red[(((ks << 4) + r) << 7) + (gcg << 2)] = st;
            }
        }
        __syncthreads();

        if (valid) {
            float2 s[4];
#pragma unroll
            for (int typ = 0; typ < 4; typ++) {
                float sx = 0.f, sy = 0.f;
#pragma unroll
                for (int k2 = 0; k2 < 8; k2++) {
                    float2 v = *(const float2*)&red[(k2 << 11) + (er << 7) + (typ << 5) + (ep << 1)];
                    sx += v.x; sy += v.y;
                }
                s[typ] = make_float2(sx, sy);
            }
            {
                float gi = s[0].x + xi.x, gf = s[1].x + xf.x, gg = s[2].x + xg2.x, go = s[3].x + xo.x;
                float cn = sigf(gf) * cc0 + sigf(gi) * tanh_fast(gg);
                cc0 = cn; hk0 = sigf(go) * tanh_fast(cn);
            }
            {
                float gi = s[0].y + xi.y, gf = s[1].y + xf.y, gg = s[2].y + xg2.y, go = s[3].y + xo.y;
                float cn = sigf(gf) * cc1 + sigf(gi) * tanh_fast(gg);
                cc1 = cn; hk1 = sigf(go) * tanh_fast(cn);
            }
        }

        *(float2*)&g_hbuf[(t + 1) & 1][(n_e << 8) + col_e] = make_float2(hk0, hk1);

        __syncthreads();
        if (tid == 0 && t + 1 < gmax) {
            asm volatile("red.release.gpu.global.add.u32 [%0], %1;"
                         :: "l"(barp), "r"(1u) : "memory");
        }
    }

    *(float2*)&out[(n_e << 8) + col_e] = make_float2(hk0, hk1);
}

// ---------------- launch ----------------
extern "C" void kernel_launch(void* const* d_in, const int* in_sizes, int n_in,
                              void* d_out, int out_size) {
    const float* attn     = (const float*)d_in[0];   // (N, T, E)
    const int*   traj_len = (const int*)d_in[1];     // (N,)
    const float* Wih      = (const float*)d_in[2];   // (4H, E)
    const float* Whh      = (const float*)d_in[3];   // (4H, H)
    const float* bih      = (const float*)d_in[4];   // (4H,)
    const float* bhh      = (const float*)d_in[5];   // (4H,)
    float* out = (float*)d_out;

    cudaFuncSetAttribute(xg_gemm_kernel, cudaFuncAttributeMaxDynamicSharedMemorySize, XG_SMEM_BYTES);
    cudaFuncSetAttribute(lstm_rec_kernel, cudaFuncAttributeMaxDynamicSharedMemorySize, 65536);

    dim3 g1(8, 1024);
    xg_gemm_kernel<<<g1, 256, XG_SMEM_BYTES>>>(attn, Wih, bih, bhh);

    lstm_rec_kernel<<<NBLK, 256, 65536>>>(Whh, traj_len, out);

    (void)in_sizes; (void)n_in; (void)out_size;
}

// round 15
// speedup vs baseline: 1.2079x; 1.2079x over previous
#include <cuda_runtime.h>
#include <cuda_bf16.h>
#include <cstdint>
#include <cstddef>

#define TT 512
#define NBATCH 256
#define EE 256
#define HH 256
#define GG 1024
#define NBLK 128
#define GSIZE 8
#define NGROUPS 16

typedef unsigned long long ull;
union F2U { ull u; float2 f; };

// ---- packed f32x2 helpers ----
__device__ __forceinline__ ull bcast2(float x) {
    ull r; asm("mov.b64 %0, {%1, %1};" : "=l"(r) : "f"(x)); return r;
}
__device__ __forceinline__ ull pack2(float lo, float hi) {
    ull r; asm("mov.b64 %0, {%1, %2};" : "=l"(r) : "f"(lo), "f"(hi)); return r;
}
__device__ __forceinline__ void ffma2(ull& d, ull a, ull b) {
    asm("fma.rn.f32x2 %0, %1, %2, %0;" : "+l"(d) : "l"(a), "l"(b));
}

// ---- warp-MMA helpers (baseline sm_100: ldmatrix + mma.sync) ----
__device__ __forceinline__ uint32_t smem_u32(const void* p) {
    uint32_t a;
    asm("{ .reg .u64 t; cvta.to.shared.u64 t, %1; cvt.u32.u64 %0, t; }" : "=r"(a) : "l"(p));
    return a;
}
__device__ __forceinline__ void ldsm_x4(uint32_t* r, uint32_t addr) {
    asm volatile("ldmatrix.sync.aligned.m8n8.x4.shared.b16 {%0,%1,%2,%3}, [%4];"
                 : "=r"(r[0]), "=r"(r[1]), "=r"(r[2]), "=r"(r[3]) : "r"(addr));
}
__device__ __forceinline__ void ldsm_x2(uint32_t* r, uint32_t addr) {
    asm volatile("ldmatrix.sync.aligned.m8n8.x2.shared.b16 {%0,%1}, [%2];"
                 : "=r"(r[0]), "=r"(r[1]) : "r"(addr));
}
__device__ __forceinline__ void mma16816(float* d, const uint32_t* a, const uint32_t* b) {
    asm volatile(
        "mma.sync.aligned.m16n8k16.row.col.f32.bf16.bf16.f32 "
        "{%0,%1,%2,%3}, {%4,%5,%6,%7}, {%8,%9}, {%0,%1,%2,%3};"
        : "+f"(d[0]), "+f"(d[1]), "+f"(d[2]), "+f"(d[3])
        : "r"(a[0]), "r"(a[1]), "r"(a[2]), "r"(a[3]), "r"(b[0]), "r"(b[1]));
}
__device__ __forceinline__ uint32_t sw128(uint32_t bo) { return bo ^ ((bo >> 3) & 0x70); }

// ---------------- device scratch ----------------
__device__ __align__(16) float g_xg[(size_t)TT * NBATCH * GG];
__device__ __align__(16) float g_hbuf[2][NBATCH * HH];
__device__ __align__(128) unsigned int g_gbar[NGROUPS * 32];

__device__ __forceinline__ void split_store(char* hi_p, char* lo_p, float4 v) {
    __nv_bfloat16 hx = __float2bfloat16(v.x), hy = __float2bfloat16(v.y),
                  hz = __float2bfloat16(v.z), hw = __float2bfloat16(v.w);
    __nv_bfloat16 lx = __float2bfloat16(v.x - __bfloat162float(hx));
    __nv_bfloat16 ly = __float2bfloat16(v.y - __bfloat162float(hy));
    __nv_bfloat16 lz = __float2bfloat16(v.z - __bfloat162float(hz));
    __nv_bfloat16 lw = __float2bfloat16(v.w - __bfloat162float(hw));
    union { __nv_bfloat162 b[2]; uint2 u; } H, L;
    H.b[0] = __halves2bfloat162(hx, hy); H.b[1] = __halves2bfloat162(hz, hw);
    L.b[0] = __halves2bfloat162(lx, ly); L.b[1] = __halves2bfloat162(lz, lw);
    *(uint2*)hi_p = H.u;
    *(uint2*)lo_p = L.u;
}

// ---------------- phase 1: xg = x @ Wih^T + biases (split-bf16 mma.sync) ----------------
// 1024 CTAs: mt = t*2 + nhalf. Each CTA: 128 batch rows x ALL 1024 gates.
// attn read ONCE (coalesced: 16 lanes = 256B contiguous of one row); A full-K
// resident in smem as hi/lo bf16 (4 k-chunk tiles, SW128). B (Wih) streamed in
// 32KB k-chunks, double-buffered, register-prefetched under the mma of the
// previous chunk. 8 warps, 2(M)x4(N) warp grid, 64x32 warp tile per gt.
__global__ void __launch_bounds__(256, 1) xg_gemm_kernel(
    const float* __restrict__ attn,   // (N, T, E)
    const float* __restrict__ Wih,    // (4H, E)
    const float* __restrict__ bih,
    const float* __restrict__ bhh) {
    extern __shared__ char dsm[];
    __shared__ float sbias[1024];

    const int mt = blockIdx.x;                 // 0..1023
    const int t  = mt >> 1;
    const int n0 = (mt & 1) << 7;
    const int tid = threadIdx.x;
    const int wid = tid >> 5, lane = tid & 31;

    // fused graph-replay-safe reset
    if (mt < 64) {
        int i = (mt << 8) + tid;
        *(float4*)&g_hbuf[0][i << 2] = make_float4(0.f, 0.f, 0.f, 0.f);
    } else if (mt == 64) {
        g_gbar[tid] = 0u;
        g_gbar[tid + 256] = 0u;
    }

    // 1024-aligned smem layout: aHi(64K) aLo(64K) B0hi(16K) B0lo(16K) B1hi(16K) B1lo(16K)
    const uint32_t dsm_u = smem_u32(dsm);
    const uint32_t base_u = (dsm_u + 1023u) & ~1023u;
    char* p = dsm + (base_u - dsm_u);
    char* aHi = p;
    char* aLo = p + 65536;
    char* bBuf = p + 131072;                   // [buf]: hi @ buf*32768, lo @ +16384
    const uint32_t uaHi = base_u, uaLo = base_u + 65536, ubBuf = base_u + 131072;

    for (int i = tid; i < 1024; i += 256) sbias[i] = bih[i] + bhh[i];

    // ---- load A (full K=256), convert, store swizzled into 4 k-chunk tiles ----
    {
        const int arow = tid >> 4;             // 0..15 within round
        const int acol = tid & 15;             // float4 col within 256B group
#pragma unroll 1
        for (int round = 0; round < 8; round++) {
            int row = (round << 4) + arow;
            const float4* src = (const float4*)(attn + ((size_t)(n0 + row) * TT + t) * EE);
#pragma unroll
            for (int q = 0; q < 4; q++) {
                int c4 = acol + (q << 4);      // float4 index 0..63
                float4 v = src[c4];
                int kch = c4 >> 4;
                uint32_t so = sw128((row << 7) + ((c4 & 15) << 3));
                split_store(aHi + kch * 16384 + so, aLo + kch * 16384 + so, v);
            }
        }
    }

    // B loader indices (coalesced: 16 lanes per row)
    const int brow_l = tid >> 4;
    const int bcol_l = tid & 15;

    float4 vb[8];
    // prefetch chunk (gt=0, kch=0)
    {
        const float* wbase = Wih;
#pragma unroll
        for (int r = 0; r < 8; r++) {
            int row = (r << 4) + brow_l;
            vb[r] = *(const float4*)(wbase + (size_t)row * EE + (bcol_l << 2));
        }
#pragma unroll
        for (int r = 0; r < 8; r++) {
            int row = (r << 4) + brow_l;
            uint32_t so = sw128((row << 7) + (bcol_l << 3));
            split_store(bBuf + so, bBuf + 16384 + so, vb[r]);
        }
    }
    __syncthreads();

    const int m_base = (wid & 1) << 6;
    const int nb     = (wid >> 1) << 5;
    const int a_r = lane & 15;
    const int a_c = (lane >> 4) << 3;
    const int b_r = lane & 7;
    const int b_c = ((lane >> 3) & 1) << 3;
    const int gID = lane >> 2, t4 = lane & 3;

    int buf = 0;

#pragma unroll 1
    for (int gt = 0; gt < 8; gt++) {
        float d[4][4][4];
#pragma unroll
        for (int mi = 0; mi < 4; mi++)
#pragma unroll
            for (int ni = 0; ni < 4; ni++)
#pragma unroll
                for (int q = 0; q < 4; q++) d[mi][ni][q] = 0.f;

#pragma unroll 1
        for (int kch = 0; kch < 4; kch++) {
            const bool have_next = !(gt == 7 && kch == 3);
            // prefetch next B chunk into registers (overlaps mma below)
            if (have_next) {
                const int ngt = gt + (kch == 3 ? 1 : 0);
                const int nkch = (kch + 1) & 3;
                const float* wbase = Wih + (size_t)(ngt << 7) * EE + (nkch << 6);
#pragma unroll
                for (int r = 0; r < 8; r++) {
                    int row = (r << 4) + brow_l;
                    vb[r] = *(const float4*)(wbase + (size_t)row * EE + (bcol_l << 2));
                }
            }

            // mma on current buffers, A chunk kch
            const uint32_t aH = uaHi + kch * 16384;
            const uint32_t aL = uaLo + kch * 16384;
            const uint32_t bH = ubBuf + buf * 32768;
            const uint32_t bL = bH + 16384;
#pragma unroll
            for (int combo = 0; combo < 3; combo++) {
                const uint32_t aBase = (combo == 2) ? aL : aH;
                const uint32_t bBase = (combo == 1) ? bL : bH;
#pragma unroll
                for (int k16 = 0; k16 < 4; k16++) {
                    const int kc = k16 << 4;
                    uint32_t afr[4][4];
#pragma unroll
                    for (int mi = 0; mi < 4; mi++) {
                        uint32_t bo = ((m_base + (mi << 4) + a_r) << 7) + ((kc + a_c) << 1);
                        ldsm_x4(afr[mi], aBase + sw128(bo));
                    }
                    uint32_t bfr[4][2];
#pragma unroll
                    for (int ni = 0; ni < 4; ni++) {
                        uint32_t bo = ((nb + (ni << 3) + b_r) << 7) + ((kc + b_c) << 1);
                        ldsm_x2(bfr[ni], bBase + sw128(bo));
                    }
#pragma unroll
                    for (int mi = 0; mi < 4; mi++)
#pragma unroll
                        for (int ni = 0; ni < 4; ni++)
                            mma16816(d[mi][ni], afr[mi], bfr[ni]);
                }
            }

            // store prefetched chunk into the other buffer (readers synced last iter)
            if (have_next) {
                char* nh = bBuf + (buf ^ 1) * 32768;
                char* nl = nh + 16384;
#pragma unroll
                for (int r = 0; r < 8; r++) {
                    int row = (r << 4) + brow_l;
                    uint32_t so = sw128((row << 7) + (bcol_l << 3));
                    split_store(nh + so, nl + so, vb[r]);
                }
            }
            __syncthreads();
            buf ^= 1;
        }

        // epilogue for this gate tile
        const int g0 = gt << 7;
#pragma unroll
        for (int mi = 0; mi < 4; mi++) {
            const int row0 = m_base + (mi << 4) + gID;
#pragma unroll
            for (int ni = 0; ni < 4; ni++) {
                const int col = nb + (ni << 3) + (t4 << 1);
                const float bx = sbias[g0 + col], by = sbias[g0 + col + 1];
                size_t base0 = ((size_t)t * NBATCH + (n0 + row0)) * GG + g0 + col;
                size_t base1 = base0 + (size_t)8 * GG;
                *(float2*)&g_xg[base0] = make_float2(d[mi][ni][0] + bx, d[mi][ni][1] + by);
                *(float2*)&g_xg[base1] = make_float2(d[mi][ni][2] + bx, d[mi][ni][3] + by);
            }
        }
    }
}

#define XG_SMEM_BYTES (196608 + 1024)

// ---------------- phase 2: persistent recurrent kernel (unchanged, validated) ----------------
__device__ __forceinline__ float sigf(float x) { return 1.0f / (1.0f + __expf(-x)); }
__device__ __forceinline__ float tanh_fast(float x) { return 1.0f - 2.0f / (__expf(2.0f * x) + 1.0f); }

__global__ void __launch_bounds__(256, 1) lstm_rec_kernel(
    const float* __restrict__ Whh,
    const int*   __restrict__ traj_len,
    float*       __restrict__ out) {
    extern __shared__ float red[];
    __shared__ float hs[16 * 256];
    __shared__ int slen[16];

    const int tid = threadIdx.x;
    const int bid = blockIdx.x;
    const int bn = bid & 15, bj = bid >> 4;
    const int r0 = bn << 4;
    const int c0 = bj << 5;
    const int ks = tid >> 5, gcg = tid & 31;

    ull pwA[32], pwB[32];
    {
        const float* wr[4];
#pragma unroll
        for (int q = 0; q < 4; q++) {
            int l = (gcg << 2) + q;
            int gr = ((l >> 5) << 8) + c0 + (l & 31);
            wr[q] = &Whh[(size_t)gr * HH + (ks << 5)];
        }
#pragma unroll
        for (int kc = 0; kc < 8; kc++) {
            float4 w0 = *(const float4*)(wr[0] + (kc << 2));
            float4 w1 = *(const float4*)(wr[1] + (kc << 2));
            float4 w2 = *(const float4*)(wr[2] + (kc << 2));
            float4 w3 = *(const float4*)(wr[3] + (kc << 2));
            pwA[(kc << 2) + 0] = pack2(w0.x, w1.x);
            pwA[(kc << 2) + 1] = pack2(w0.y, w1.y);
            pwA[(kc << 2) + 2] = pack2(w0.z, w1.z);
            pwA[(kc << 2) + 3] = pack2(w0.w, w1.w);
            pwB[(kc << 2) + 0] = pack2(w2.x, w3.x);
            pwB[(kc << 2) + 1] = pack2(w2.y, w3.y);
            pwB[(kc << 2) + 2] = pack2(w2.z, w3.z);
            pwB[(kc << 2) + 3] = pack2(w2.w, w3.w);
        }
    }

    if (tid < 16) slen[tid] = traj_len[r0 + tid];

    const int er = tid >> 4, ep = tid & 15;
    const int n_e = r0 + er;
    const int len_e = traj_len[n_e];
    const int col_e = c0 + (ep << 1);
    float cc0 = 0.f, cc1 = 0.f, hk0 = 0.f, hk1 = 0.f;

    unsigned int* barp = &g_gbar[bn << 5];
    __syncthreads();

    int gmax = 0;
#pragma unroll
    for (int r = 0; r < 16; r++) gmax = max(gmax, slen[r]);

    for (int t = 0; t < gmax; t++) {
        const bool valid = (t < len_e);

        float2 xi, xf, xg2, xo;
        if (valid) {
            const float* xgp = &g_xg[((size_t)t * NBATCH + n_e) * GG + col_e];
            xi  = __ldcs((const float2*)&xgp[0]);
            xf  = __ldcs((const float2*)&xgp[256]);
            xg2 = __ldcs((const float2*)&xgp[512]);
            xo  = __ldcs((const float2*)&xgp[768]);
        }

        if (t > 0) {
            if (tid == 0) {
                const unsigned target = (unsigned)t * GSIZE;
                unsigned v;
                do {
                    asm volatile("ld.acquire.gpu.global.u32 %0, [%1];"
                                 : "=r"(v) : "l"(barp) : "memory");
                } while (v < target);
            }
            __syncthreads();
        }

        {
            const float4* src = (const float4*)&g_hbuf[t & 1][r0 << 8];
#pragma unroll
            for (int q = 0; q < 4; q++) {
                int i = (q << 8) + tid;
                float4 v = __ldcg(src + i);
                *(float4*)&hs[i << 2] = v;
            }
        }
        __syncthreads();

#pragma unroll 2
        for (int r = 0; r < 16; r++) {
            if (t < slen[r]) {
                const float4* hp = (const float4*)&hs[(r << 8) + (ks << 5)];
                ull accA = 0ull, accB = 0ull;
#pragma unroll
                for (int kc = 0; kc < 8; kc++) {
                    float4 hv = hp[kc];
                    ull h0 = bcast2(hv.x), h1 = bcast2(hv.y), h2 = bcast2(hv.z), h3 = bcast2(hv.w);
                    ffma2(accA, h0, pwA[(kc << 2) + 0]); ffma2(accB, h0, pwB[(kc << 2) + 0]);
                    ffma2(accA, h1, pwA[(kc << 2) + 1]); ffma2(accB, h1, pwB[(kc << 2) + 1]);
                    ffma2(accA, h2, pwA[(kc << 2) + 2]); ffma2(accB, h2, pwB[(kc << 2) + 2]);
                    ffma2(accA, h3, pwA[(kc << 2) + 3]); ffma2(accB, h3, pwB[(kc << 2) + 3]);
                }
                ulonglong2 st; st.x = accA; st.y = accB;
                *(ulonglong2*)&red[(((ks << 4) + r) << 7) + (gcg << 2)] = st;
            }
        }
        __syncthreads();

        if (valid) {
            float2 s[4];
#pragma unroll
            for (int typ = 0; typ < 4; typ++) {
                float sx = 0.f, sy = 0.f;
#pragma unroll
                for (int k2 = 0; k2 < 8; k2++) {
                    float2 v = *(const float2*)&red[(k2 << 11) + (er << 7) + (typ << 5) + (ep << 1)];
                    sx += v.x; sy += v.y;
                }
                s[typ] = make_float2(sx, sy);
            }
            {
                float gi = s[0].x + xi.x, gf = s[1].x + xf.x, gg = s[2].x + xg2.x, go = s[3].x + xo.x;
                float cn = sigf(gf) * cc0 + sigf(gi) * tanh_fast(gg);
                cc0 = cn; hk0 = sigf(go) * tanh_fast(cn);
            }
            {
                float gi = s[0].y + xi.y, gf = s[1].y + xf.y, gg = s[2].y + xg2.y, go = s[3].y + xo.y;
                float cn = sigf(gf) * cc1 + sigf(gi) * tanh_fast(gg);
                cc1 = cn; hk1 = sigf(go) * tanh_fast(cn);
            }
        }

        *(float2*)&g_hbuf[(t + 1) & 1][(n_e << 8) + col_e] = make_float2(hk0, hk1);

        __syncthreads();
        if (tid == 0 && t + 1 < gmax) {
            asm volatile("red.release.gpu.global.add.u32 [%0], %1;"
                         :: "l"(barp), "r"(1u) : "memory");
        }
    }

    *(float2*)&out[(n_e << 8) + col_e] = make_float2(hk0, hk1);
}

// ---------------- launch ----------------
extern "C" void kernel_launch(void* const* d_in, const int* in_sizes, int n_in,
                              void* d_out, int out_size) {
    const float* attn     = (const float*)d_in[0];
    const int*   traj_len = (const int*)d_in[1];
    const float* Wih      = (const float*)d_in[2];
    const float* Whh      = (const float*)d_in[3];
    const float* bih      = (const float*)d_in[4];
    const float* bhh      = (const float*)d_in[5];
    float* out = (float*)d_out;

    cudaFuncSetAttribute(xg_gemm_kernel, cudaFuncAttributeMaxDynamicSharedMemorySize, XG_SMEM_BYTES);
    cudaFuncSetAttribute(lstm_rec_kernel, cudaFuncAttributeMaxDynamicSharedMemorySize, 65536);

    xg_gemm_kernel<<<1024, 256, XG_SMEM_BYTES>>>(attn, Wih, bih, bhh);

    lstm_rec_kernel<<<NBLK, 256, 65536>>>(Whh, traj_len, out);

    (void)in_sizes; (void)n_in; (void)out_size;
}